// round 10
// baseline (speedup 1.0000x reference)
#include <cuda_runtime.h>
#include <cuda_fp16.h>
#include <cstdint>
#include <cstddef>

#define LSEQ 2048
#define DMODEL 1024
#define DI 2048
#define DSTATE 16
#define DTRANK 64
#define HIDF 4096
#define NPROJ 96

// ------------------------------------------------------------------
// scratch (device globals; no allocation allowed)
// ------------------------------------------------------------------
__device__ float  g_xz[LSEQ * 2 * DI];
__device__ float  g_xc[LSEQ * DI];
__device__ float  g_proj[LSEQ * NPROJ];
__device__ float2 g_dx[LSEQ * DI];          // (delta, delta*xc)
__device__ float2 g_bc[LSEQ * DSTATE];      // (B, C)
__device__ float  g_ys[LSEQ * DI];
__device__ float  g_h[LSEQ * DMODEL];
__device__ float  g_n[LSEQ * DMODEL];

// fp16 activations, TILE-PACKED layout (128x64 swizzled tiles)
__device__ __half g_hln_h[LSEQ * DMODEL];
__device__ __half g_xc_h[LSEQ * DI];
__device__ __half g_y_h[LSEQ * DI];
__device__ __half g_n_h[LSEQ * DMODEL];
__device__ __half g_f1_h[LSEQ * HIDF];

// fp16 weights, TILE-PACKED (rows padded to multiple of 128)
__device__ __half g_win_h[2 * DI * DMODEL];
__device__ __half g_wxp_h[128 * DI];
__device__ __half g_wout_h[DMODEL * DI];
__device__ __half g_wf1_h[HIDF * DMODEL];
__device__ __half g_wf2_h[DMODEL * HIDF];

// ------------------------------------------------------------------
// packed-tile addressing (128x64 fp16 tiles, SW128-swizzled quads)
// ------------------------------------------------------------------
__device__ __forceinline__ size_t pk(int row, int col, int ldk) {
    size_t t = (size_t)(row >> 7) * (ldk >> 6) + (col >> 6);
    const int r = row & 127;
    return t * 8192 + r * 64 + ((((col >> 3) & 7) ^ (r & 7)) << 3) + (col & 7);
}

// ------------------------------------------------------------------
// PTX helpers
// ------------------------------------------------------------------
__device__ __forceinline__ uint32_t smem_u32(const void* p) {
    uint32_t a;
    asm("{ .reg .u64 t; cvta.to.shared.u64 t, %1; cvt.u32.u64 %0, t; }" : "=r"(a) : "l"(p));
    return a;
}
__device__ __forceinline__ void mbar_init(uint32_t a, uint32_t cnt) {
    asm volatile("mbarrier.init.shared.b64 [%0], %1;" :: "r"(a), "r"(cnt) : "memory");
}
__device__ __forceinline__ void mbar_expect_tx(uint32_t a, uint32_t bytes) {
    asm volatile("mbarrier.arrive.expect_tx.shared.b64 _, [%0], %1;"
                 :: "r"(a), "r"(bytes) : "memory");
}
__device__ __forceinline__ void mbar_wait(uint32_t a, uint32_t parity) {
    asm volatile(
        "{\n\t.reg .pred P;\n\t"
        "WL_%=:\n\t"
        "mbarrier.try_wait.parity.acquire.cta.shared::cta.b64 P, [%0], %1, 0x989680;\n\t"
        "@P bra.uni WD_%=;\n\t"
        "bra.uni WL_%=;\n\t"
        "WD_%=:\n\t}"
        :: "r"(a), "r"(parity) : "memory");
}
__device__ __forceinline__ void bulk_g2s(uint32_t dst, const void* src, uint32_t bytes, uint32_t mbar) {
    asm volatile(
        "cp.async.bulk.shared::cta.global.mbarrier::complete_tx::bytes [%0], [%1], %2, [%3];"
        :: "r"(dst), "l"(src), "r"(bytes), "r"(mbar) : "memory");
}
__device__ __forceinline__ void ldsm_x4(uint32_t addr, uint32_t* r) {
    asm volatile("ldmatrix.sync.aligned.m8n8.x4.shared.b16 {%0,%1,%2,%3}, [%4];"
                 : "=r"(r[0]), "=r"(r[1]), "=r"(r[2]), "=r"(r[3]) : "r"(addr));
}
__device__ __forceinline__ void mma_f16(float* c, const uint32_t* a, const uint32_t* b) {
    asm volatile(
        "mma.sync.aligned.m16n8k16.row.col.f32.f16.f16.f32 "
        "{%0,%1,%2,%3}, {%4,%5,%6,%7}, {%8,%9}, {%0,%1,%2,%3};"
        : "+f"(c[0]), "+f"(c[1]), "+f"(c[2]), "+f"(c[3])
        : "r"(a[0]), "r"(a[1]), "r"(a[2]), "r"(a[3]), "r"(b[0]), "r"(b[1]));
}
__device__ __forceinline__ uint32_t sw128(uint32_t bo) { return bo ^ ((bo >> 3) & 0x70); }

// ------------------------------------------------------------------
// GEMM: C[M,N] = A[M,K] @ W[N,K]^T, packed fp16 operands, fp32 accum.
// BMx128 CTA tile, 4 warps (warp tile BM/2 x 64), k-chunk 64,
// 3-stage bulk-copy ring. 128 threads, 2 CTAs/SM.
// modes: 0 store f32 | 1 +res1 f32 | 2 bias+relu -> packed fp16 | 3 bias+res1+res2 f32
// ------------------------------------------------------------------
template<int BM>
__global__ __launch_bounds__(128, 2)
void tc_gemm(const __half* __restrict__ Apk, const __half* __restrict__ Bpk,
             float* __restrict__ C, __half* __restrict__ Oh,
             int ldc, int N, int K, int mode,
             const float* __restrict__ bias,
             const float* __restrict__ res1, int ldr1,
             const float* __restrict__ res2, int ldr2) {
    constexpr int MF = BM / 32;                   // m-frags (16 rows) per warp
    constexpr int ABYTES = BM * 128;
    constexpr int STB = ABYTES + 16384;           // stage bytes (A + B tile)
    extern __shared__ char smem[];
    const uint32_t sb = smem_u32(smem);           // 3 mbarriers at sb+0/8/16
    const uint32_t tiles = sb + 1024;
    const int tid = threadIdx.x;
    const int wid = tid >> 5, lid = tid & 31;
    const int bm = blockIdx.y * BM;
    const int bn = blockIdx.x * 128;
    const int wm = (wid & 1) * (BM / 2);
    const int wn = (wid >> 1) * 64;
    const int nch = K >> 6;
    const size_t aBase = (size_t)(bm >> 7) * nch * 8192 + (size_t)((bm >> 6) & 1) * 4096;
    const size_t bBase = (size_t)(bn >> 7) * nch * 8192;

    if (tid == 0) {
        mbar_init(sb + 0, 1); mbar_init(sb + 8, 1); mbar_init(sb + 16, 1);
        asm volatile("fence.proxy.async.shared::cta;" ::: "memory");
    }
    __syncthreads();

    float acc[MF][8][4];
#pragma unroll
    for (int mf = 0; mf < MF; ++mf)
#pragma unroll
        for (int nf = 0; nf < 8; ++nf)
#pragma unroll
            for (int v = 0; v < 4; ++v) acc[mf][nf][v] = 0.0f;

    const int mat = lid >> 3;
    const int lrow = lid & 7;
    const int rowA = wm + (mat & 1) * 8 + lrow;
    const int kqA = (mat >> 1);
    const int rowB = wn + (mat >> 1) * 8 + lrow;
    const int kqB = (mat & 1);

    if (tid == 0) {
#pragma unroll
        for (int c = 0; c < 2; ++c) {
            const uint32_t mb = sb + c * 8;
            const uint32_t dst = tiles + c * STB;
            mbar_expect_tx(mb, STB);
            bulk_g2s(dst, Apk + aBase + (size_t)c * 8192, ABYTES, mb);
            bulk_g2s(dst + ABYTES, Bpk + bBase + (size_t)c * 8192, 16384, mb);
        }
    }

    for (int c = 0; c < nch; ++c) {
        if (tid == 0 && c + 2 < nch) {
            const int s = (c + 2) % 3;
            const uint32_t mb = sb + s * 8;
            const uint32_t dst = tiles + s * STB;
            mbar_expect_tx(mb, STB);
            bulk_g2s(dst, Apk + aBase + (size_t)(c + 2) * 8192, ABYTES, mb);
            bulk_g2s(dst + ABYTES, Bpk + bBase + (size_t)(c + 2) * 8192, 16384, mb);
        }
        mbar_wait(sb + (c % 3) * 8, (uint32_t)((c / 3) & 1));

        const uint32_t base = tiles + (c % 3) * STB;
#pragma unroll
        for (int ks = 0; ks < 4; ++ks) {
            uint32_t ah[MF][4], bf[16];
#pragma unroll
            for (int mf = 0; mf < MF; ++mf) {
                const uint32_t bo = (uint32_t)(rowA + mf * 16) * 128 + ks * 32 + kqA * 16;
                ldsm_x4(base + sw128(bo), ah[mf]);
            }
#pragma unroll
            for (int p = 0; p < 4; ++p) {
                const uint32_t bo = (uint32_t)(rowB + p * 16) * 128 + ks * 32 + kqB * 16;
                ldsm_x4(base + ABYTES + sw128(bo), &bf[p * 4]);
            }
#pragma unroll
            for (int mf = 0; mf < MF; ++mf)
#pragma unroll
                for (int nf = 0; nf < 8; ++nf)
                    mma_f16(acc[mf][nf], ah[mf], &bf[nf * 2]);
        }
        __syncthreads();
    }

    const int erow0 = bm + wm + (lid >> 2);
    const int ecol0 = bn + wn + (lid & 3) * 2;
#pragma unroll
    for (int mf = 0; mf < MF; ++mf)
#pragma unroll
        for (int nf = 0; nf < 8; ++nf)
#pragma unroll
            for (int half = 0; half < 2; ++half) {
                const int row = erow0 + mf * 16 + half * 8;
                const int col = ecol0 + nf * 8;
                if (col >= N) continue;
                float v0 = acc[mf][nf][half * 2 + 0];
                float v1 = acc[mf][nf][half * 2 + 1];
                if (mode == 0) {
                    *(float2*)(C + (size_t)row * ldc + col) = make_float2(v0, v1);
                } else if (mode == 1) {
                    const float2 rr = *(const float2*)(res1 + (size_t)row * ldr1 + col);
                    *(float2*)(C + (size_t)row * ldc + col) = make_float2(v0 + rr.x, v1 + rr.y);
                } else if (mode == 2) {
                    const float2 bb = *(const float2*)(bias + col);
                    v0 = fmaxf(v0 + bb.x, 0.f);
                    v1 = fmaxf(v1 + bb.y, 0.f);
                    *(__half2*)(Oh + pk(row, col, ldc)) =
                        __half2(__float2half_rn(v0), __float2half_rn(v1));
                } else {
                    const float2 bb = *(const float2*)(bias + col);
                    const float2 r1 = *(const float2*)(res1 + (size_t)row * ldr1 + col);
                    const float2 r2 = *(const float2*)(res2 + (size_t)row * ldr2 + col);
                    *(float2*)(C + (size_t)row * ldc + col) =
                        make_float2(v0 + bb.x + r1.x + r2.x, v1 + bb.y + r1.y + r2.y);
                }
            }
}

// ------------------------------------------------------------------
// LayerNorm (D=1024): optional fp32 out + packed fp16 out
// ------------------------------------------------------------------
__global__ void ln_kernel(const float* __restrict__ x, const float* __restrict__ g,
                          const float* __restrict__ b, float* __restrict__ outf,
                          __half* __restrict__ oh) {
    __shared__ float rs[8], rq[8];
    const int tid = threadIdx.x;
    const size_t base = (size_t)blockIdx.x * DMODEL;
    float4 xv = *(const float4*)(x + base + tid * 4);
    float s = xv.x + xv.y + xv.z + xv.w;
    float q = xv.x * xv.x + xv.y * xv.y + xv.z * xv.z + xv.w * xv.w;
#pragma unroll
    for (int o = 16; o > 0; o >>= 1) {
        s += __shfl_xor_sync(0xffffffffu, s, o);
        q += __shfl_xor_sync(0xffffffffu, q, o);
    }
    if ((tid & 31) == 0) { rs[tid >> 5] = s; rq[tid >> 5] = q; }
    __syncthreads();
    s = rs[0] + rs[1] + rs[2] + rs[3] + rs[4] + rs[5] + rs[6] + rs[7];
    q = rq[0] + rq[1] + rq[2] + rq[3] + rq[4] + rq[5] + rq[6] + rq[7];
    const float mu = s * (1.0f / DMODEL);
    const float var = q * (1.0f / DMODEL) - mu * mu;
    const float rstd = rsqrtf(var + 1e-5f);
    float4 gv = *(const float4*)(g + tid * 4);
    float4 bv = *(const float4*)(b + tid * 4);
    float o0 = (xv.x - mu) * rstd * gv.x + bv.x;
    float o1 = (xv.y - mu) * rstd * gv.y + bv.y;
    float o2 = (xv.z - mu) * rstd * gv.z + bv.z;
    float o3 = (xv.w - mu) * rstd * gv.w + bv.w;
    if (outf) *(float4*)(outf + base + tid * 4) = make_float4(o0, o1, o2, o3);
    const int col = tid * 4;
    __half2* ph = (__half2*)(oh + pk(blockIdx.x, col, DMODEL));
    ph[0] = __half2(__float2half_rn(o0), __float2half_rn(o1));
    ph[1] = __half2(__float2half_rn(o2), __float2half_rn(o3));
}

// ------------------------------------------------------------------
// fused weight fp32 -> packed fp16 (all 5 weights in one launch)
// ------------------------------------------------------------------
#define N4_WIN  (2 * DI * DMODEL / 4)
#define N4_WXP  (NPROJ * DI / 4)
#define N4_WOUT (DMODEL * DI / 4)
#define N4_WF1  (HIDF * DMODEL / 4)
#define N4_WF2  (DMODEL * HIDF / 4)
#define N4_ALL  (N4_WIN + N4_WXP + N4_WOUT + N4_WF1 + N4_WF2)

__global__ void cvt_all(const float4* __restrict__ win, const float4* __restrict__ wxp,
                        const float4* __restrict__ wout, const float4* __restrict__ wf1,
                        const float4* __restrict__ wf2) {
    int i = blockIdx.x * blockDim.x + threadIdx.x;
    const float4* src;
    __half* dst;
    int kshift;
    if (i < N4_WIN) { src = win; dst = g_win_h; kshift = 10; }
    else if ((i -= N4_WIN) < N4_WXP) { src = wxp; dst = g_wxp_h; kshift = 11; }
    else if ((i -= N4_WXP) < N4_WOUT) { src = wout; dst = g_wout_h; kshift = 11; }
    else if ((i -= N4_WOUT) < N4_WF1) { src = wf1; dst = g_wf1_h; kshift = 10; }
    else if ((i -= N4_WF1) < N4_WF2) { src = wf2; dst = g_wf2_h; kshift = 12; }
    else return;
    const float4 v = src[i];
    const int e = i << 2;
    const int row = e >> kshift;
    const int col = e & ((1 << kshift) - 1);
    __half2* p = (__half2*)(dst + pk(row, col, 1 << kshift));
    p[0] = __half2(__float2half_rn(v.x), __float2half_rn(v.y));
    p[1] = __half2(__float2half_rn(v.z), __float2half_rn(v.w));
}

// ------------------------------------------------------------------
// causal depthwise conv + SiLU -> xc fp32 + packed fp16
// ------------------------------------------------------------------
__global__ void conv_silu_kernel(const float* __restrict__ conv_w, const float* __restrict__ conv_b) {
    const int idx = blockIdx.x * blockDim.x + threadIdx.x;
    const int d = idx & (DI - 1);
    const int t = idx >> 11;
    float acc = conv_b[d];
#pragma unroll
    for (int k = 0; k < 4; ++k) {
        const int tt = t + k - 3;
        if (tt >= 0) acc = fmaf(g_xz[(size_t)tt * (2 * DI) + d], conv_w[d * 4 + k], acc);
    }
    const float v = acc / (1.0f + __expf(-acc));
    g_xc[idx] = v;
    g_xc_h[pk(t, d, DI)] = __float2half_rn(v);
}

// ------------------------------------------------------------------
// pack (B, C) from proj
// ------------------------------------------------------------------
__global__ void pack_bc_kernel() {
    const int i = blockIdx.x * blockDim.x + threadIdx.x;   // L*16
    const int t = i >> 4, s = i & 15;
    g_bc[i] = make_float2(g_proj[t * NPROJ + DTRANK + s],
                          g_proj[t * NPROJ + DTRANK + DSTATE + s]);
}

// ------------------------------------------------------------------
// delta GEMM (SIMT, K=64): dx = (softplus(dt @ Wdt^T + b), delta*xc)
// ------------------------------------------------------------------
__global__ __launch_bounds__(256, 2)
void delta_gemm(const float* __restrict__ P, const float* __restrict__ W,
                const float* __restrict__ bias) {
    __shared__ float As[8][128];
    __shared__ float Bs[8][128];
    const int tid = threadIdx.x;
    const int bm = blockIdx.y * 128;
    const int bn = blockIdx.x * 128;
    const int aRow = tid >> 1, aCol = (tid & 1) * 4;
    const int tx = tid & 15, ty = tid >> 4;
    float acc[8][8];
#pragma unroll
    for (int i = 0; i < 8; ++i)
#pragma unroll
        for (int j = 0; j < 8; ++j) acc[i][j] = 0.0f;
    for (int k0 = 0; k0 < 64; k0 += 8) {
        float4 av = *(const float4*)(P + (size_t)(bm + aRow) * NPROJ + k0 + aCol);
        float4 bv = *(const float4*)(W + (size_t)(bn + aRow) * 64 + k0 + aCol);
        __syncthreads();
        As[aCol + 0][aRow] = av.x; As[aCol + 1][aRow] = av.y;
        As[aCol + 2][aRow] = av.z; As[aCol + 3][aRow] = av.w;
        Bs[aCol + 0][aRow] = bv.x; Bs[aCol + 1][aRow] = bv.y;
        Bs[aCol + 2][aRow] = bv.z; Bs[aCol + 3][aRow] = bv.w;
        __syncthreads();
#pragma unroll
        for (int kk = 0; kk < 8; ++kk) {
            float rm[8], rn[8];
            *(float4*)&rm[0] = *(const float4*)&As[kk][ty * 8];
            *(float4*)&rm[4] = *(const float4*)&As[kk][ty * 8 + 4];
            *(float4*)&rn[0] = *(const float4*)&Bs[kk][tx * 8];
            *(float4*)&rn[4] = *(const float4*)&Bs[kk][tx * 8 + 4];
#pragma unroll
            for (int i = 0; i < 8; ++i)
#pragma unroll
                for (int j = 0; j < 8; ++j) acc[i][j] = fmaf(rm[i], rn[j], acc[i][j]);
        }
    }
#pragma unroll
    for (int i = 0; i < 8; ++i) {
        const int row = bm + ty * 8 + i;
#pragma unroll
        for (int j = 0; j < 8; ++j) {
            const int col = bn + tx * 8 + j;
            float v = acc[i][j] + bias[col];
            v = fmaxf(v, 0.0f) + log1pf(__expf(-fabsf(v)));
            const float xcv = g_xc[(size_t)row * DI + col];
            g_dx[(size_t)row * DI + col] = make_float2(v, v * xcv);
        }
    }
}

// ------------------------------------------------------------------
// selective scan: 16 lanes per channel, batch-8 timesteps,
// fully unrolled (register-resident buffers), deferred shfl reductions
// ------------------------------------------------------------------
__global__ void scan_kernel(const float* __restrict__ A_log) {
    const int s = threadIdx.x & 15;
    const int d = blockIdx.x * 16 + (threadIdx.x >> 4);
    const float a = -__expf(A_log[d * DSTATE + s]);
    float h = 0.0f;

    float2 cd[8], cb[8], nd[8], nb[8];
#pragma unroll
    for (int j = 0; j < 8; ++j) {
        cd[j] = g_dx[(size_t)j * DI + d];
        cb[j] = g_bc[j * DSTATE + s];
        nd[j] = make_float2(0.f, 0.f);
        nb[j] = make_float2(0.f, 0.f);
    }

    for (int t0 = 0; t0 < LSEQ; t0 += 8) {
        if (t0 + 8 < LSEQ) {
#pragma unroll
            for (int j = 0; j < 8; ++j) {
                nd[j] = g_dx[(size_t)(t0 + 8 + j) * DI + d];
                nb[j] = g_bc[(t0 + 8 + j) * DSTATE + s];
            }
        }
        float p[8];
#pragma unroll
        for (int j = 0; j < 8; ++j) {
            h = fmaf(h, __expf(a * cd[j].x), cd[j].y * cb[j].x);
            p[j] = h * cb[j].y;
        }
#pragma unroll
        for (int o = 1; o <= 8; o <<= 1)
#pragma unroll
            for (int j = 0; j < 8; ++j)
                p[j] += __shfl_xor_sync(0xffffffffu, p[j], o);
        if (s == 0) {
#pragma unroll
            for (int j = 0; j < 8; ++j)
                g_ys[(size_t)(t0 + j) * DI + d] = p[j];
        }
#pragma unroll
        for (int j = 0; j < 8; ++j) { cd[j] = nd[j]; cb[j] = nb[j]; }
    }
}

// ------------------------------------------------------------------
// y = (ys + xc*Dp) * silu(z) -> packed fp16
// ------------------------------------------------------------------
__global__ void ygate_kernel(const float* __restrict__ Dp) {
    const int idx = blockIdx.x * blockDim.x + threadIdx.x;
    const int d = idx & (DI - 1);
    const int t = idx >> 11;
    const float z = g_xz[(size_t)t * (2 * DI) + DI + d];
    const float sig = 1.0f / (1.0f + __expf(-z));
    const float v = fmaf(g_xc[idx], Dp[d], g_ys[idx]) * (z * sig);
    g_y_h[pk(t, d, DI)] = __float2half_rn(v);
}

// ------------------------------------------------------------------
// launch
// ------------------------------------------------------------------
#define SMEM_BIG   (1024 + 3 * (128 * 128 + 16384))   // 99328
#define SMEM_SMALL (1024 + 3 * (64 * 128 + 16384))    // 74752

extern "C" void kernel_launch(void* const* d_in, const int* in_sizes, int n_in,
                              void* d_out, int out_size) {
    const float* x         = (const float*)d_in[0];
    const float* ln1_g     = (const float*)d_in[1];
    const float* ln1_b     = (const float*)d_in[2];
    const float* ln2_g     = (const float*)d_in[3];
    const float* ln2_b     = (const float*)d_in[4];
    const float* in_proj_w = (const float*)d_in[5];
    const float* conv_w    = (const float*)d_in[6];
    const float* conv_b    = (const float*)d_in[7];
    const float* x_proj_w  = (const float*)d_in[8];
    const float* dt_proj_w = (const float*)d_in[9];
    const float* dt_proj_b = (const float*)d_in[10];
    const float* A_log     = (const float*)d_in[11];
    const float* D_param   = (const float*)d_in[12];
    const float* out_proj_w= (const float*)d_in[13];
    const float* ffn_w1    = (const float*)d_in[14];
    const float* ffn_b1    = (const float*)d_in[15];
    const float* ffn_w2    = (const float*)d_in[16];
    const float* ffn_b2    = (const float*)d_in[17];
    float* out = (float*)d_out;

    cudaFuncSetAttribute(tc_gemm<128>, cudaFuncAttributeMaxDynamicSharedMemorySize, SMEM_BIG);
    cudaFuncSetAttribute(tc_gemm<64>,  cudaFuncAttributeMaxDynamicSharedMemorySize, SMEM_SMALL);

#define SYM(p, s) void* p; cudaGetSymbolAddress(&p, s)
    SYM(p_xz, g_xz); SYM(p_proj, g_proj); SYM(p_h, g_h); SYM(p_n, g_n);
    SYM(p_hln_h, g_hln_h);
    SYM(p_xc_h, g_xc_h);
    SYM(p_y_h, g_y_h);
    SYM(p_n_h, g_n_h);
    SYM(p_f1_h, g_f1_h);
    SYM(p_win_h, g_win_h);
    SYM(p_wxp_h, g_wxp_h);
    SYM(p_wout_h, g_wout_h);
    SYM(p_wf1_h, g_wf1_h);
    SYM(p_wf2_h, g_wf2_h);
#undef SYM

    // 1) all weight conversions in one launch
    cvt_all<<<(N4_ALL + 255) / 256, 256>>>((const float4*)in_proj_w, (const float4*)x_proj_w,
                                           (const float4*)out_proj_w, (const float4*)ffn_w1,
                                           (const float4*)ffn_w2);

    // 2) LN1 -> hln (packed fp16)
    ln_kernel<<<LSEQ, 256>>>(x, ln1_g, ln1_b, nullptr, (__half*)p_hln_h);

    // 3) xz = hln @ in_proj_w^T   [2048, 4096]
    tc_gemm<128><<<dim3(32, 16), 128, SMEM_BIG>>>(
        (__half*)p_hln_h, (__half*)p_win_h,
        (float*)p_xz, nullptr, 2 * DI, 2 * DI, DMODEL, 0,
        nullptr, nullptr, 0, nullptr, 0);

    // 4) conv + silu -> xc (fp32 + packed fp16)
    conv_silu_kernel<<<(LSEQ * DI) / 256, 256>>>(conv_w, conv_b);

    // 5) proj = xc @ x_proj_w^T   [2048, 96]
    tc_gemm<64><<<dim3(1, 32), 128, SMEM_SMALL>>>(
        (__half*)p_xc_h, (__half*)p_wxp_h,
        (float*)p_proj, nullptr, NPROJ, NPROJ, DI, 0,
        nullptr, nullptr, 0, nullptr, 0);

    // 6) pack (B, C)
    pack_bc_kernel<<<(LSEQ * DSTATE) / 256, 256>>>();

    // 7) delta = softplus(dt @ dt_proj_w^T + b); dx = (delta, delta*xc)
    delta_gemm<<<dim3(DI / 128, LSEQ / 128), 256>>>((const float*)p_proj, dt_proj_w, dt_proj_b);

    // 8) selective scan (batched)
    scan_kernel<<<DI / 16, 256>>>(A_log);

    // 9) y gate -> y (packed fp16)
    ygate_kernel<<<(LSEQ * DI) / 256, 256>>>(D_param);

    // 10) h = y @ out_proj_w^T + x   [2048, 1024]
    tc_gemm<64><<<dim3(8, 32), 128, SMEM_SMALL>>>(
        (__half*)p_y_h, (__half*)p_wout_h,
        (float*)p_h, nullptr, DMODEL, DMODEL, DI, 1,
        nullptr, x, DMODEL, nullptr, 0);

    // 11) LN2 -> n (fp32 + packed fp16)
    ln_kernel<<<LSEQ, 256>>>((const float*)p_h, ln2_g, ln2_b, (float*)p_n, (__half*)p_n_h);

    // 12) f1 = relu(n @ ffn_w1^T + b1) -> packed fp16   [2048, 4096]
    tc_gemm<128><<<dim3(32, 16), 128, SMEM_BIG>>>(
        (__half*)p_n_h, (__half*)p_wf1_h,
        nullptr, (__half*)p_f1_h, HIDF, HIDF, DMODEL, 2,
        ffn_b1, nullptr, 0, nullptr, 0);

    // 13) out = f1 @ ffn_w2^T + b2 + n + h   [2048, 1024]
    tc_gemm<64><<<dim3(8, 32), 128, SMEM_SMALL>>>(
        (__half*)p_f1_h, (__half*)p_wf2_h,
        out, nullptr, DMODEL, DMODEL, HIDF, 3,
        ffn_b2, (const float*)p_n, DMODEL, (const float*)p_h, DMODEL);
}

// round 11
// speedup vs baseline: 1.4427x; 1.4427x over previous
#include <cuda_runtime.h>
#include <cuda_fp16.h>
#include <cstdint>
#include <cstddef>

#define LSEQ 2048
#define DMODEL 1024
#define DI 2048
#define DSTATE 16
#define DTRANK 64
#define HIDF 4096
#define NPROJ 96

// ------------------------------------------------------------------
// scratch (device globals; no allocation allowed)
// ------------------------------------------------------------------
__device__ float  g_xz[LSEQ * 2 * DI];
__device__ float  g_xc[LSEQ * DI];
__device__ float  g_proj[LSEQ * NPROJ];
__device__ float2 g_dx[LSEQ * DI];          // (delta, delta*xc)
__device__ float2 g_bc[LSEQ * DSTATE];      // (B, C)
__device__ float  g_ys[LSEQ * DI];
__device__ float  g_h[LSEQ * DMODEL];
__device__ float  g_n[LSEQ * DMODEL];

// fp16 activations, TILE-PACKED layout (128x64 swizzled tiles)
__device__ __half g_hln_h[LSEQ * DMODEL];
__device__ __half g_xc_h[LSEQ * DI];
__device__ __half g_y_h[LSEQ * DI];
__device__ __half g_n_h[LSEQ * DMODEL];
__device__ __half g_f1_h[LSEQ * HIDF];

// fp16 weights, TILE-PACKED (rows padded to multiple of 128)
__device__ __half g_win_h[2 * DI * DMODEL];
__device__ __half g_wxp_h[128 * DI];
__device__ __half g_wout_h[DMODEL * DI];
__device__ __half g_wf1_h[HIDF * DMODEL];
__device__ __half g_wf2_h[DMODEL * HIDF];

// ------------------------------------------------------------------
// packed-tile addressing (128x64 fp16 tiles, SW128-swizzled quads)
// ------------------------------------------------------------------
__device__ __forceinline__ size_t pk(int row, int col, int ldk) {
    size_t t = (size_t)(row >> 7) * (ldk >> 6) + (col >> 6);
    const int r = row & 127;
    return t * 8192 + r * 64 + ((((col >> 3) & 7) ^ (r & 7)) << 3) + (col & 7);
}

// ------------------------------------------------------------------
// PTX helpers
// ------------------------------------------------------------------
__device__ __forceinline__ uint32_t smem_u32(const void* p) {
    uint32_t a;
    asm("{ .reg .u64 t; cvta.to.shared.u64 t, %1; cvt.u32.u64 %0, t; }" : "=r"(a) : "l"(p));
    return a;
}
__device__ __forceinline__ void mbar_init(uint32_t a, uint32_t cnt) {
    asm volatile("mbarrier.init.shared.b64 [%0], %1;" :: "r"(a), "r"(cnt) : "memory");
}
__device__ __forceinline__ void mbar_expect_tx(uint32_t a, uint32_t bytes) {
    asm volatile("mbarrier.arrive.expect_tx.shared.b64 _, [%0], %1;"
                 :: "r"(a), "r"(bytes) : "memory");
}
__device__ __forceinline__ void mbar_wait(uint32_t a, uint32_t parity) {
    asm volatile(
        "{\n\t.reg .pred P;\n\t"
        "WL_%=:\n\t"
        "mbarrier.try_wait.parity.acquire.cta.shared::cta.b64 P, [%0], %1, 0x989680;\n\t"
        "@P bra.uni WD_%=;\n\t"
        "bra.uni WL_%=;\n\t"
        "WD_%=:\n\t}"
        :: "r"(a), "r"(parity) : "memory");
}
__device__ __forceinline__ void bulk_g2s(uint32_t dst, const void* src, uint32_t bytes, uint32_t mbar) {
    asm volatile(
        "cp.async.bulk.shared::cta.global.mbarrier::complete_tx::bytes [%0], [%1], %2, [%3];"
        :: "r"(dst), "l"(src), "r"(bytes), "r"(mbar) : "memory");
}
__device__ __forceinline__ void ldsm_x4(uint32_t addr, uint32_t* r) {
    asm volatile("ldmatrix.sync.aligned.m8n8.x4.shared.b16 {%0,%1,%2,%3}, [%4];"
                 : "=r"(r[0]), "=r"(r[1]), "=r"(r[2]), "=r"(r[3]) : "r"(addr));
}
__device__ __forceinline__ void mma_f16(float* c, const uint32_t* a, const uint32_t* b) {
    asm volatile(
        "mma.sync.aligned.m16n8k16.row.col.f32.f16.f16.f32 "
        "{%0,%1,%2,%3}, {%4,%5,%6,%7}, {%8,%9}, {%0,%1,%2,%3};"
        : "+f"(c[0]), "+f"(c[1]), "+f"(c[2]), "+f"(c[3])
        : "r"(a[0]), "r"(a[1]), "r"(a[2]), "r"(a[3]), "r"(b[0]), "r"(b[1]));
}
__device__ __forceinline__ uint32_t sw128(uint32_t bo) { return bo ^ ((bo >> 3) & 0x70); }

// ------------------------------------------------------------------
// GEMM: C[M,N] = A[M,K] @ W[N,K]^T, packed fp16 operands, fp32 accum.
// BMx128 CTA tile, 4 warps (warp tile BM/2 x 64), k-chunk 64,
// 3-stage bulk-copy ring. 128 threads, 2 CTAs/SM.
// modes: 0 store f32 | 1 +res1 f32 | 2 bias+relu -> packed fp16 | 3 bias+res1+res2 f32
// ------------------------------------------------------------------
template<int BM>
__global__ __launch_bounds__(128, 2)
void tc_gemm(const __half* __restrict__ Apk, const __half* __restrict__ Bpk,
             float* __restrict__ C, __half* __restrict__ Oh,
             int ldc, int N, int K, int mode,
             const float* __restrict__ bias,
             const float* __restrict__ res1, int ldr1,
             const float* __restrict__ res2, int ldr2) {
    constexpr int MF = BM / 32;                   // m-frags (16 rows) per warp
    constexpr int ABYTES = BM * 128;
    constexpr int STB = ABYTES + 16384;           // stage bytes (A + B tile)
    extern __shared__ char smem[];
    const uint32_t sb = smem_u32(smem);           // 3 mbarriers at sb+0/8/16
    const uint32_t tiles = sb + 1024;
    const int tid = threadIdx.x;
    const int wid = tid >> 5, lid = tid & 31;
    const int bm = blockIdx.y * BM;
    const int bn = blockIdx.x * 128;
    const int wm = (wid & 1) * (BM / 2);
    const int wn = (wid >> 1) * 64;
    const int nch = K >> 6;
    const size_t aBase = (size_t)(bm >> 7) * nch * 8192 + (size_t)((bm >> 6) & 1) * 4096;
    const size_t bBase = (size_t)(bn >> 7) * nch * 8192;

    if (tid == 0) {
        mbar_init(sb + 0, 1); mbar_init(sb + 8, 1); mbar_init(sb + 16, 1);
        asm volatile("fence.proxy.async.shared::cta;" ::: "memory");
    }
    __syncthreads();

    float acc[MF][8][4];
#pragma unroll
    for (int mf = 0; mf < MF; ++mf)
#pragma unroll
        for (int nf = 0; nf < 8; ++nf)
#pragma unroll
            for (int v = 0; v < 4; ++v) acc[mf][nf][v] = 0.0f;

    const int mat = lid >> 3;
    const int lrow = lid & 7;
    const int rowA = wm + (mat & 1) * 8 + lrow;
    const int kqA = (mat >> 1);
    const int rowB = wn + (mat >> 1) * 8 + lrow;
    const int kqB = (mat & 1);

    if (tid == 0) {
#pragma unroll
        for (int c = 0; c < 2; ++c) {
            const uint32_t mb = sb + c * 8;
            const uint32_t dst = tiles + c * STB;
            mbar_expect_tx(mb, STB);
            bulk_g2s(dst, Apk + aBase + (size_t)c * 8192, ABYTES, mb);
            bulk_g2s(dst + ABYTES, Bpk + bBase + (size_t)c * 8192, 16384, mb);
        }
    }

    for (int c = 0; c < nch; ++c) {
        if (tid == 0 && c + 2 < nch) {
            const int s = (c + 2) % 3;
            const uint32_t mb = sb + s * 8;
            const uint32_t dst = tiles + s * STB;
            mbar_expect_tx(mb, STB);
            bulk_g2s(dst, Apk + aBase + (size_t)(c + 2) * 8192, ABYTES, mb);
            bulk_g2s(dst + ABYTES, Bpk + bBase + (size_t)(c + 2) * 8192, 16384, mb);
        }
        mbar_wait(sb + (c % 3) * 8, (uint32_t)((c / 3) & 1));

        const uint32_t base = tiles + (c % 3) * STB;
#pragma unroll
        for (int ks = 0; ks < 4; ++ks) {
            uint32_t ah[MF][4], bf[16];
#pragma unroll
            for (int mf = 0; mf < MF; ++mf) {
                const uint32_t bo = (uint32_t)(rowA + mf * 16) * 128 + ks * 32 + kqA * 16;
                ldsm_x4(base + sw128(bo), ah[mf]);
            }
#pragma unroll
            for (int p = 0; p < 4; ++p) {
                const uint32_t bo = (uint32_t)(rowB + p * 16) * 128 + ks * 32 + kqB * 16;
                ldsm_x4(base + ABYTES + sw128(bo), &bf[p * 4]);
            }
#pragma unroll
            for (int mf = 0; mf < MF; ++mf)
#pragma unroll
                for (int nf = 0; nf < 8; ++nf)
                    mma_f16(acc[mf][nf], ah[mf], &bf[nf * 2]);
        }
        __syncthreads();
    }

    const int erow0 = bm + wm + (lid >> 2);
    const int ecol0 = bn + wn + (lid & 3) * 2;
#pragma unroll
    for (int mf = 0; mf < MF; ++mf)
#pragma unroll
        for (int nf = 0; nf < 8; ++nf)
#pragma unroll
            for (int half = 0; half < 2; ++half) {
                const int row = erow0 + mf * 16 + half * 8;
                const int col = ecol0 + nf * 8;
                if (col >= N) continue;
                float v0 = acc[mf][nf][half * 2 + 0];
                float v1 = acc[mf][nf][half * 2 + 1];
                if (mode == 0) {
                    *(float2*)(C + (size_t)row * ldc + col) = make_float2(v0, v1);
                } else if (mode == 1) {
                    const float2 rr = *(const float2*)(res1 + (size_t)row * ldr1 + col);
                    *(float2*)(C + (size_t)row * ldc + col) = make_float2(v0 + rr.x, v1 + rr.y);
                } else if (mode == 2) {
                    const float2 bb = *(const float2*)(bias + col);
                    v0 = fmaxf(v0 + bb.x, 0.f);
                    v1 = fmaxf(v1 + bb.y, 0.f);
                    *(__half2*)(Oh + pk(row, col, ldc)) =
                        __half2(__float2half_rn(v0), __float2half_rn(v1));
                } else {
                    const float2 bb = *(const float2*)(bias + col);
                    const float2 r1 = *(const float2*)(res1 + (size_t)row * ldr1 + col);
                    const float2 r2 = *(const float2*)(res2 + (size_t)row * ldr2 + col);
                    *(float2*)(C + (size_t)row * ldc + col) =
                        make_float2(v0 + bb.x + r1.x + r2.x, v1 + bb.y + r1.y + r2.y);
                }
            }
}

// ------------------------------------------------------------------
// LayerNorm (D=1024): optional fp32 out + packed fp16 out
// ------------------------------------------------------------------
__global__ void ln_kernel(const float* __restrict__ x, const float* __restrict__ g,
                          const float* __restrict__ b, float* __restrict__ outf,
                          __half* __restrict__ oh) {
    __shared__ float rs[8], rq[8];
    const int tid = threadIdx.x;
    const size_t base = (size_t)blockIdx.x * DMODEL;
    float4 xv = *(const float4*)(x + base + tid * 4);
    float s = xv.x + xv.y + xv.z + xv.w;
    float q = xv.x * xv.x + xv.y * xv.y + xv.z * xv.z + xv.w * xv.w;
#pragma unroll
    for (int o = 16; o > 0; o >>= 1) {
        s += __shfl_xor_sync(0xffffffffu, s, o);
        q += __shfl_xor_sync(0xffffffffu, q, o);
    }
    if ((tid & 31) == 0) { rs[tid >> 5] = s; rq[tid >> 5] = q; }
    __syncthreads();
    s = rs[0] + rs[1] + rs[2] + rs[3] + rs[4] + rs[5] + rs[6] + rs[7];
    q = rq[0] + rq[1] + rq[2] + rq[3] + rq[4] + rq[5] + rq[6] + rq[7];
    const float mu = s * (1.0f / DMODEL);
    const float var = q * (1.0f / DMODEL) - mu * mu;
    const float rstd = rsqrtf(var + 1e-5f);
    float4 gv = *(const float4*)(g + tid * 4);
    float4 bv = *(const float4*)(b + tid * 4);
    float o0 = (xv.x - mu) * rstd * gv.x + bv.x;
    float o1 = (xv.y - mu) * rstd * gv.y + bv.y;
    float o2 = (xv.z - mu) * rstd * gv.z + bv.z;
    float o3 = (xv.w - mu) * rstd * gv.w + bv.w;
    if (outf) *(float4*)(outf + base + tid * 4) = make_float4(o0, o1, o2, o3);
    const int col = tid * 4;
    __half2* ph = (__half2*)(oh + pk(blockIdx.x, col, DMODEL));
    ph[0] = __half2(__float2half_rn(o0), __float2half_rn(o1));
    ph[1] = __half2(__float2half_rn(o2), __float2half_rn(o3));
}

// ------------------------------------------------------------------
// weight fp32 -> packed fp16 (4 elems/thread)
// ------------------------------------------------------------------
__global__ void cvt_h(const float4* __restrict__ src, __half* __restrict__ dst,
                      int n4, int kshift) {
    const int i = blockIdx.x * blockDim.x + threadIdx.x;
    if (i < n4) {
        const float4 v = src[i];
        const int e = i << 2;
        const int row = e >> kshift;
        const int col = e & ((1 << kshift) - 1);
        __half2* p = (__half2*)(dst + pk(row, col, 1 << kshift));
        p[0] = __half2(__float2half_rn(v.x), __float2half_rn(v.y));
        p[1] = __half2(__float2half_rn(v.z), __float2half_rn(v.w));
    }
}

// ------------------------------------------------------------------
// causal depthwise conv + SiLU -> xc fp32 + packed fp16
// ------------------------------------------------------------------
__global__ void conv_silu_kernel(const float* __restrict__ conv_w, const float* __restrict__ conv_b) {
    const int idx = blockIdx.x * blockDim.x + threadIdx.x;
    const int d = idx & (DI - 1);
    const int t = idx >> 11;
    float acc = conv_b[d];
#pragma unroll
    for (int k = 0; k < 4; ++k) {
        const int tt = t + k - 3;
        if (tt >= 0) acc = fmaf(g_xz[(size_t)tt * (2 * DI) + d], conv_w[d * 4 + k], acc);
    }
    const float v = acc / (1.0f + __expf(-acc));
    g_xc[idx] = v;
    g_xc_h[pk(t, d, DI)] = __float2half_rn(v);
}

// ------------------------------------------------------------------
// pack (B, C) from proj
// ------------------------------------------------------------------
__global__ void pack_bc_kernel() {
    const int i = blockIdx.x * blockDim.x + threadIdx.x;   // L*16
    const int t = i >> 4, s = i & 15;
    g_bc[i] = make_float2(g_proj[t * NPROJ + DTRANK + s],
                          g_proj[t * NPROJ + DTRANK + DSTATE + s]);
}

// ------------------------------------------------------------------
// delta GEMM (SIMT, K=64): dx = (softplus(dt @ Wdt^T + b), delta*xc)
// ------------------------------------------------------------------
__global__ __launch_bounds__(256, 2)
void delta_gemm(const float* __restrict__ P, const float* __restrict__ W,
                const float* __restrict__ bias) {
    __shared__ float As[8][128];
    __shared__ float Bs[8][128];
    const int tid = threadIdx.x;
    const int bm = blockIdx.y * 128;
    const int bn = blockIdx.x * 128;
    const int aRow = tid >> 1, aCol = (tid & 1) * 4;
    const int tx = tid & 15, ty = tid >> 4;
    float acc[8][8];
#pragma unroll
    for (int i = 0; i < 8; ++i)
#pragma unroll
        for (int j = 0; j < 8; ++j) acc[i][j] = 0.0f;
    for (int k0 = 0; k0 < 64; k0 += 8) {
        float4 av = *(const float4*)(P + (size_t)(bm + aRow) * NPROJ + k0 + aCol);
        float4 bv = *(const float4*)(W + (size_t)(bn + aRow) * 64 + k0 + aCol);
        __syncthreads();
        As[aCol + 0][aRow] = av.x; As[aCol + 1][aRow] = av.y;
        As[aCol + 2][aRow] = av.z; As[aCol + 3][aRow] = av.w;
        Bs[aCol + 0][aRow] = bv.x; Bs[aCol + 1][aRow] = bv.y;
        Bs[aCol + 2][aRow] = bv.z; Bs[aCol + 3][aRow] = bv.w;
        __syncthreads();
#pragma unroll
        for (int kk = 0; kk < 8; ++kk) {
            float rm[8], rn[8];
            *(float4*)&rm[0] = *(const float4*)&As[kk][ty * 8];
            *(float4*)&rm[4] = *(const float4*)&As[kk][ty * 8 + 4];
            *(float4*)&rn[0] = *(const float4*)&Bs[kk][tx * 8];
            *(float4*)&rn[4] = *(const float4*)&Bs[kk][tx * 8 + 4];
#pragma unroll
            for (int i = 0; i < 8; ++i)
#pragma unroll
                for (int j = 0; j < 8; ++j) acc[i][j] = fmaf(rm[i], rn[j], acc[i][j]);
        }
    }
#pragma unroll
    for (int i = 0; i < 8; ++i) {
        const int row = bm + ty * 8 + i;
#pragma unroll
        for (int j = 0; j < 8; ++j) {
            const int col = bn + tx * 8 + j;
            float v = acc[i][j] + bias[col];
            v = fmaxf(v, 0.0f) + log1pf(__expf(-fabsf(v)));
            const float xcv = g_xc[(size_t)row * DI + col];
            g_dx[(size_t)row * DI + col] = make_float2(v, v * xcv);
        }
    }
}

// ------------------------------------------------------------------
// selective scan: 16 lanes per channel, batch-8 timesteps,
// fully unrolled (register-resident buffers), deferred shfl reductions
// ------------------------------------------------------------------
__global__ void scan_kernel(const float* __restrict__ A_log) {
    const int s = threadIdx.x & 15;
    const int d = blockIdx.x * 16 + (threadIdx.x >> 4);
    const float a = -__expf(A_log[d * DSTATE + s]);
    float h = 0.0f;

    float2 cd[8], cb[8], nd[8], nb[8];
#pragma unroll
    for (int j = 0; j < 8; ++j) {
        cd[j] = g_dx[(size_t)j * DI + d];
        cb[j] = g_bc[j * DSTATE + s];
        nd[j] = make_float2(0.f, 0.f);
        nb[j] = make_float2(0.f, 0.f);
    }

    for (int t0 = 0; t0 < LSEQ; t0 += 8) {
        if (t0 + 8 < LSEQ) {
#pragma unroll
            for (int j = 0; j < 8; ++j) {
                nd[j] = g_dx[(size_t)(t0 + 8 + j) * DI + d];
                nb[j] = g_bc[(t0 + 8 + j) * DSTATE + s];
            }
        }
        float p[8];
#pragma unroll
        for (int j = 0; j < 8; ++j) {
            h = fmaf(h, __expf(a * cd[j].x), cd[j].y * cb[j].x);
            p[j] = h * cb[j].y;
        }
#pragma unroll
        for (int o = 1; o <= 8; o <<= 1)
#pragma unroll
            for (int j = 0; j < 8; ++j)
                p[j] += __shfl_xor_sync(0xffffffffu, p[j], o);
        if (s == 0) {
#pragma unroll
            for (int j = 0; j < 8; ++j)
                g_ys[(size_t)(t0 + j) * DI + d] = p[j];
        }
#pragma unroll
        for (int j = 0; j < 8; ++j) { cd[j] = nd[j]; cb[j] = nb[j]; }
    }
}

// ------------------------------------------------------------------
// y = (ys + xc*Dp) * silu(z) -> packed fp16
// ------------------------------------------------------------------
__global__ void ygate_kernel(const float* __restrict__ Dp) {
    const int idx = blockIdx.x * blockDim.x + threadIdx.x;
    const int d = idx & (DI - 1);
    const int t = idx >> 11;
    const float z = g_xz[(size_t)t * (2 * DI) + DI + d];
    const float sig = 1.0f / (1.0f + __expf(-z));
    const float v = fmaf(g_xc[idx], Dp[d], g_ys[idx]) * (z * sig);
    g_y_h[pk(t, d, DI)] = __float2half_rn(v);
}

// ------------------------------------------------------------------
// launch
// ------------------------------------------------------------------
#define SMEM_BIG   (1024 + 3 * (128 * 128 + 16384))   // 99328
#define SMEM_SMALL (1024 + 3 * (64 * 128 + 16384))    // 74752

extern "C" void kernel_launch(void* const* d_in, const int* in_sizes, int n_in,
                              void* d_out, int out_size) {
    const float* x         = (const float*)d_in[0];
    const float* ln1_g     = (const float*)d_in[1];
    const float* ln1_b     = (const float*)d_in[2];
    const float* ln2_g     = (const float*)d_in[3];
    const float* ln2_b     = (const float*)d_in[4];
    const float* in_proj_w = (const float*)d_in[5];
    const float* conv_w    = (const float*)d_in[6];
    const float* conv_b    = (const float*)d_in[7];
    const float* x_proj_w  = (const float*)d_in[8];
    const float* dt_proj_w = (const float*)d_in[9];
    const float* dt_proj_b = (const float*)d_in[10];
    const float* A_log     = (const float*)d_in[11];
    const float* D_param   = (const float*)d_in[12];
    const float* out_proj_w= (const float*)d_in[13];
    const float* ffn_w1    = (const float*)d_in[14];
    const float* ffn_b1    = (const float*)d_in[15];
    const float* ffn_w2    = (const float*)d_in[16];
    const float* ffn_b2    = (const float*)d_in[17];
    float* out = (float*)d_out;

    cudaFuncSetAttribute(tc_gemm<128>, cudaFuncAttributeMaxDynamicSharedMemorySize, SMEM_BIG);
    cudaFuncSetAttribute(tc_gemm<64>,  cudaFuncAttributeMaxDynamicSharedMemorySize, SMEM_SMALL);

#define SYM(p, s) void* p; cudaGetSymbolAddress(&p, s)
    SYM(p_xz, g_xz); SYM(p_proj, g_proj); SYM(p_h, g_h); SYM(p_n, g_n);
    SYM(p_hln_h, g_hln_h);
    SYM(p_xc_h, g_xc_h);
    SYM(p_y_h, g_y_h);
    SYM(p_n_h, g_n_h);
    SYM(p_f1_h, g_f1_h);
    SYM(p_win_h, g_win_h);
    SYM(p_wxp_h, g_wxp_h);
    SYM(p_wout_h, g_wout_h);
    SYM(p_wf1_h, g_wf1_h);
    SYM(p_wf2_h, g_wf2_h);
#undef SYM

    // weight conversions into packed-tile layout
    cvt_h<<<(2 * DI * DMODEL / 4 + 255) / 256, 256>>>((const float4*)in_proj_w, (__half*)p_win_h, 2 * DI * DMODEL / 4, 10);
    cvt_h<<<(NPROJ * DI / 4 + 255) / 256, 256>>>((const float4*)x_proj_w, (__half*)p_wxp_h, NPROJ * DI / 4, 11);
    cvt_h<<<(DMODEL * DI / 4 + 255) / 256, 256>>>((const float4*)out_proj_w, (__half*)p_wout_h, DMODEL * DI / 4, 11);
    cvt_h<<<(HIDF * DMODEL / 4 + 255) / 256, 256>>>((const float4*)ffn_w1, (__half*)p_wf1_h, HIDF * DMODEL / 4, 10);
    cvt_h<<<(DMODEL * HIDF / 4 + 255) / 256, 256>>>((const float4*)ffn_w2, (__half*)p_wf2_h, DMODEL * HIDF / 4, 12);

    // 1) LN1 -> hln (packed fp16)
    ln_kernel<<<LSEQ, 256>>>(x, ln1_g, ln1_b, nullptr, (__half*)p_hln_h);

    // 2) xz = hln @ in_proj_w^T   [2048, 4096]
    tc_gemm<128><<<dim3(32, 16), 128, SMEM_BIG>>>(
        (__half*)p_hln_h, (__half*)p_win_h,
        (float*)p_xz, nullptr, 2 * DI, 2 * DI, DMODEL, 0,
        nullptr, nullptr, 0, nullptr, 0);

    // 3) conv + silu -> xc (fp32 + packed fp16)
    conv_silu_kernel<<<(LSEQ * DI) / 256, 256>>>(conv_w, conv_b);

    // 4) proj = xc @ x_proj_w^T   [2048, 96]
    tc_gemm<64><<<dim3(1, 32), 128, SMEM_SMALL>>>(
        (__half*)p_xc_h, (__half*)p_wxp_h,
        (float*)p_proj, nullptr, NPROJ, NPROJ, DI, 0,
        nullptr, nullptr, 0, nullptr, 0);

    // 5) pack (B, C)
    pack_bc_kernel<<<(LSEQ * DSTATE) / 256, 256>>>();

    // 6) delta = softplus(dt @ dt_proj_w^T + b); dx = (delta, delta*xc)
    delta_gemm<<<dim3(DI / 128, LSEQ / 128), 256>>>((const float*)p_proj, dt_proj_w, dt_proj_b);

    // 7) selective scan (batched)
    scan_kernel<<<DI / 16, 256>>>(A_log);

    // 8) y gate -> y (packed fp16)
    ygate_kernel<<<(LSEQ * DI) / 256, 256>>>(D_param);

    // 9) h = y @ out_proj_w^T + x   [2048, 1024]
    tc_gemm<64><<<dim3(8, 32), 128, SMEM_SMALL>>>(
        (__half*)p_y_h, (__half*)p_wout_h,
        (float*)p_h, nullptr, DMODEL, DMODEL, DI, 1,
        nullptr, x, DMODEL, nullptr, 0);

    // 10) LN2 -> n (fp32 + packed fp16)
    ln_kernel<<<LSEQ, 256>>>((const float*)p_h, ln2_g, ln2_b, (float*)p_n, (__half*)p_n_h);

    // 11) f1 = relu(n @ ffn_w1^T + b1) -> packed fp16   [2048, 4096]
    tc_gemm<128><<<dim3(32, 16), 128, SMEM_BIG>>>(
        (__half*)p_n_h, (__half*)p_wf1_h,
        nullptr, (__half*)p_f1_h, HIDF, HIDF, DMODEL, 2,
        ffn_b1, nullptr, 0, nullptr, 0);

    // 12) out = f1 @ ffn_w2^T + b2 + n + h   [2048, 1024]
    tc_gemm<64><<<dim3(8, 32), 128, SMEM_SMALL>>>(
        (__half*)p_f1_h, (__half*)p_wf2_h,
        out, nullptr, DMODEL, DMODEL, HIDF, 3,
        ffn_b2, (const float*)p_n, DMODEL, (const float*)p_h, DMODEL);
}